// round 4
// baseline (speedup 1.0000x reference)
#include <cuda_runtime.h>
#include <cuda_fp16.h>
#include <math.h>

#define NN 1000000
#define NE 16000000
#define SCAN_CHUNK 1024
#define NB1 977            // ceil(NN / 1024)

// ---- scratch (device globals) ----
__device__ float   g_deg[NN];
__device__ int     g_cnt[NN];
__device__ float   g_dis[NN];        // rsqrt(deg+1)
__device__ int     g_off[NN];        // CSR start per dst node
__device__ int     g_cur[NN];        // fill cursors (copy of g_off)
__device__ int     g_bsum[NB1];
__device__ int     g_boff[NB1];
__device__ int2    g_csr[NE];        // {src, bitcast(w)} sorted by dst
__device__ __half2 g_hs[NN * 8];     // dis[i]*h[i], 16 fp16 features
__device__ float   g_h2s[NN];        // dis[i]*h2[i]

// ---------------- phase 0: degree + count ----------------

__global__ void k_zero() {
    int i = blockIdx.x * blockDim.x + threadIdx.x;
    if (i < NN) { g_deg[i] = 0.0f; g_cnt[i] = 0; }
}

__global__ void k_deg(const int4* __restrict__ dst4,
                      const float4* __restrict__ ew4) {
    int t = blockIdx.x * blockDim.x + threadIdx.x;
    if (t >= NE / 4) return;
    int4 d = __ldcs(dst4 + t);
    float4 w = __ldcs(ew4 + t);
    if ((unsigned)d.x < NN) { atomicAdd(&g_deg[d.x], w.x); atomicAdd(&g_cnt[d.x], 1); }
    if ((unsigned)d.y < NN) { atomicAdd(&g_deg[d.y], w.y); atomicAdd(&g_cnt[d.y], 1); }
    if ((unsigned)d.z < NN) { atomicAdd(&g_deg[d.z], w.z); atomicAdd(&g_cnt[d.z], 1); }
    if ((unsigned)d.w < NN) { atomicAdd(&g_deg[d.w], w.w); atomicAdd(&g_cnt[d.w], 1); }
}

__global__ void k_dis() {
    int i = blockIdx.x * blockDim.x + threadIdx.x;
    if (i < NN) g_dis[i] = rsqrtf(g_deg[i] + 1.0f);
}

// ---------------- phase 1: exclusive scan of g_cnt (3 kernels) ----------------

__global__ void k_scan1() {   // per-1024-chunk sums; 256 thr, 4 elem/thr
    int b = blockIdx.x, t = threadIdx.x;
    int base = b * SCAN_CHUNK + t * 4;
    int sum = 0;
#pragma unroll
    for (int j = 0; j < 4; j++) { int idx = base + j; if (idx < NN) sum += g_cnt[idx]; }
    __shared__ int wsum[8];
#pragma unroll
    for (int o = 16; o > 0; o >>= 1) sum += __shfl_down_sync(~0u, sum, o);
    if ((t & 31) == 0) wsum[t >> 5] = sum;
    __syncthreads();
    if (t < 8) {
        int v = wsum[t];
#pragma unroll
        for (int o = 4; o > 0; o >>= 1) v += __shfl_down_sync(0xff, v, o);
        if (t == 0) g_bsum[b] = v;
    }
}

__global__ void k_scan2() {   // single block, exclusive scan of NB1 chunk sums
    __shared__ int sh[1024];
    int t = threadIdx.x;
    int v = (t < NB1) ? g_bsum[t] : 0;
    sh[t] = v;
    __syncthreads();
    for (int o = 1; o < 1024; o <<= 1) {
        int add = (t >= o) ? sh[t - o] : 0;
        __syncthreads();
        sh[t] += add;
        __syncthreads();
    }
    if (t < NB1) g_boff[t] = sh[t] - v;
}

__global__ void k_scan3() {   // local exclusive scan + chunk base -> g_off, g_cur
    int b = blockIdx.x, t = threadIdx.x;
    int base = b * SCAN_CHUNK + t * 4;
    int v[4], p[4], s = 0;
#pragma unroll
    for (int j = 0; j < 4; j++) {
        int idx = base + j;
        v[j] = (idx < NN) ? g_cnt[idx] : 0;
        p[j] = s; s += v[j];
    }
    int lane = t & 31, wid = t >> 5;
    int incl = s;
#pragma unroll
    for (int o = 1; o < 32; o <<= 1) { int n = __shfl_up_sync(~0u, incl, o); if (lane >= o) incl += n; }
    int wexcl = incl - s;
    __shared__ int wtot[8], wbase[8];
    if (lane == 31) wtot[wid] = incl;
    __syncthreads();
    if (t < 8) {
        int x = wtot[t], inc = x;
#pragma unroll
        for (int o = 1; o < 8; o <<= 1) { int n = __shfl_up_sync(0xff, inc, o); if (t >= o) inc += n; }
        wbase[t] = inc - x;
    }
    __syncthreads();
    int tb = g_boff[b] + wbase[wid] + wexcl;
#pragma unroll
    for (int j = 0; j < 4; j++) {
        int idx = base + j;
        if (idx < NN) { int off = tb + p[j]; g_off[idx] = off; g_cur[idx] = off; }
    }
}

// ---------------- phase 2: CSR fill ----------------

__global__ void k_fill(const int4* __restrict__ src4,
                       const int4* __restrict__ dst4,
                       const float4* __restrict__ ew4) {
    int t = blockIdx.x * blockDim.x + threadIdx.x;
    if (t >= NE / 4) return;
    int4 s = __ldcs(src4 + t);
    int4 d = __ldcs(dst4 + t);
    float4 w = __ldcs(ew4 + t);
    if ((unsigned)s.x < NN && (unsigned)d.x < NN) g_csr[atomicAdd(&g_cur[d.x], 1)] = make_int2(s.x, __float_as_int(w.x));
    if ((unsigned)s.y < NN && (unsigned)d.y < NN) g_csr[atomicAdd(&g_cur[d.y], 1)] = make_int2(s.y, __float_as_int(w.y));
    if ((unsigned)s.z < NN && (unsigned)d.z < NN) g_csr[atomicAdd(&g_cur[d.z], 1)] = make_int2(s.z, __float_as_int(w.z));
    if ((unsigned)s.w < NN && (unsigned)d.w < NN) g_csr[atomicAdd(&g_cur[d.w], 1)] = make_int2(s.w, __float_as_int(w.w));
}

// ---------------- phase 3: projection h = x@W1, store dis*h as fp16 ----------------

__global__ void __launch_bounds__(256) k_proj1(const float* __restrict__ x,
                                               const float* __restrict__ W1) {
    __shared__ float sx[256 * 25];
    __shared__ float sW[25 * 16];
    int i0 = blockIdx.x * 256;
    int nb = min(256, NN - i0);
    int nf4 = (nb * 25) / 4;
    const float4* xg = (const float4*)(x + (size_t)i0 * 25);
    for (int t = threadIdx.x; t < nf4; t += 256) ((float4*)sx)[t] = __ldcs(xg + t);
    for (int t = threadIdx.x; t < 400; t += 256) sW[t] = W1[t];
    __syncthreads();

    int li = threadIdx.x;
    if (li >= nb) return;
    int i = i0 + li;

    float a[16];
#pragma unroll
    for (int f = 0; f < 16; f++) a[f] = 0.0f;
#pragma unroll
    for (int k = 0; k < 25; k++) {
        float xv = sx[li * 25 + k];
#pragma unroll
        for (int f = 0; f < 16; f++) a[f] = fmaf(xv, sW[k * 16 + f], a[f]);
    }

    float s = g_dis[i];
    size_t hb = (size_t)i * 8;
#pragma unroll
    for (int q = 0; q < 8; q++)
        g_hs[hb + q] = __floats2half2_rn(s * a[2*q], s * a[2*q + 1]);
}

// ---------------- phase 4: layer-1 pull + ELU + @W2 fused ----------------

__device__ __forceinline__ void acc_hs(float acc[16], int srcn, float w) {
    const uint4* hp = (const uint4*)(g_hs + (size_t)srcn * 8);
    uint4 p0 = __ldg(hp);
    uint4 p1 = __ldg(hp + 1);
    const unsigned* pu = &p0.x;
#pragma unroll
    for (int q = 0; q < 4; q++) {
        float2 f = __half22float2(*(const __half2*)&pu[q]);
        acc[2*q]   = fmaf(w, f.x, acc[2*q]);
        acc[2*q+1] = fmaf(w, f.y, acc[2*q+1]);
    }
    const unsigned* pv = &p1.x;
#pragma unroll
    for (int q = 0; q < 4; q++) {
        float2 f = __half22float2(*(const __half2*)&pv[q]);
        acc[8+2*q]   = fmaf(w, f.x, acc[8+2*q]);
        acc[8+2*q+1] = fmaf(w, f.y, acc[8+2*q+1]);
    }
}

__global__ void k_l1(const float* __restrict__ b1,
                     const float* __restrict__ W2) {
    __shared__ float sb1[16], sW2[16];
    if (threadIdx.x < 16) { sb1[threadIdx.x] = b1[threadIdx.x]; sW2[threadIdx.x] = W2[threadIdx.x]; }
    __syncthreads();

    int i = blockIdx.x * blockDim.x + threadIdx.x;
    if (i >= NN) return;

    int off = g_off[i], cnt = g_cnt[i];
    float acc[16];
#pragma unroll
    for (int f = 0; f < 16; f++) acc[f] = 0.0f;

    for (int k = 0; k < cnt; k++) {
        int2 rec = __ldcs(&g_csr[off + k]);
        acc_hs(acc, rec.x, __int_as_float(rec.y));
    }
    acc_hs(acc, i, 1.0f);              // self loop (dis_i * h_i, fp16)

    float s = g_dis[i];
    float h2 = 0.0f;
#pragma unroll
    for (int f = 0; f < 16; f++) {
        float u = fmaf(s, acc[f], sb1[f]);
        u = (u > 0.0f) ? u : expm1f(u);     // ELU alpha=1
        h2 = fmaf(u, sW2[f], h2);
    }
    g_h2s[i] = s * h2;                      // dis_i * h2_i
}

// ---------------- phase 5: layer-2 pull + bias fused ----------------

__global__ void k_l2(const float* __restrict__ b2, float* __restrict__ out) {
    int i = blockIdx.x * blockDim.x + threadIdx.x;
    if (i >= NN) return;
    int off = g_off[i], cnt = g_cnt[i];
    float a = 0.0f;
    for (int k = 0; k < cnt; k++) {
        int2 rec = __ldcs(&g_csr[off + k]);
        a = fmaf(__int_as_float(rec.y), __ldg(&g_h2s[rec.x]), a);
    }
    a += g_h2s[i];                          // self loop
    out[i] = fmaf(g_dis[i], a, b2[0]);
}

// ---------------- launch ----------------

extern "C" void kernel_launch(void* const* d_in, const int* in_sizes, int n_in,
                              void* d_out, int out_size) {
    const float* x    = (const float*)d_in[0];
    const int*   eidx = (const int*)d_in[1];      // [2, E] int32
    const float* ew   = (const float*)d_in[2];
    const float* W1   = (const float*)d_in[3];
    const float* b1   = (const float*)d_in[4];
    const float* W2   = (const float*)d_in[5];
    const float* b2   = (const float*)d_in[6];
    float* out = (float*)d_out;

    const int4*   src4 = (const int4*)eidx;
    const int4*   dst4 = (const int4*)(eidx + NE);
    const float4* ew4  = (const float4*)ew;

    const int TB = 256;
    int nb_nodes = (NN + TB - 1) / TB;
    int nb_e4    = (NE / 4 + TB - 1) / TB;

    k_zero<<<nb_nodes, TB>>>();
    k_deg<<<nb_e4, TB>>>(dst4, ew4);
    k_dis<<<nb_nodes, TB>>>();
    k_scan1<<<NB1, 256>>>();
    k_scan2<<<1, 1024>>>();
    k_scan3<<<NB1, 256>>>();
    k_fill<<<nb_e4, TB>>>(src4, dst4, ew4);
    k_proj1<<<nb_nodes, TB>>>(x, W1);
    k_l1<<<nb_nodes, TB>>>(b1, W2);
    k_l2<<<nb_nodes, TB>>>(b2, out);
}

// round 5
// speedup vs baseline: 1.6565x; 1.6565x over previous
#include <cuda_runtime.h>
#include <cuda_fp16.h>
#include <math.h>

#define NN 1000000
#define NE 16000000

// ---- scratch (device globals) ----
__device__ float   g_deg[NN];
__device__ __half2 g_hs[NN * 8];     // dis[i]*h[i], 16 fp16 features (gather pool, 32MB)
__device__ __half2 g_agg[NN * 8];    // layer-1 accumulation in fp16 (RMW pool, 32MB)
__device__ float   g_h2s[NN];        // dis[i]*h2[i]

// ---------------- kernels ----------------

__global__ void k_zero() {
    int i = blockIdx.x * blockDim.x + threadIdx.x;
    if (i < NN) g_deg[i] = 0.0f;
}

// per edge: accumulate weighted degree at dst
__global__ void k_deg(const int4* __restrict__ dst4,
                      const float4* __restrict__ ew4) {
    int t = blockIdx.x * blockDim.x + threadIdx.x;
    if (t >= NE / 4) return;
    int4 d = __ldcs(dst4 + t);
    float4 w = __ldcs(ew4 + t);
    if ((unsigned)d.x < NN) atomicAdd(&g_deg[d.x], w.x);
    if ((unsigned)d.y < NN) atomicAdd(&g_deg[d.y], w.y);
    if ((unsigned)d.z < NN) atomicAdd(&g_deg[d.z], w.z);
    if ((unsigned)d.w < NN) atomicAdd(&g_deg[d.w], w.w);
}

// h = x @ W1 (smem-staged x tile); store g_hs = dis*h (fp16), seed g_agg = same (self loop)
__global__ void __launch_bounds__(256) k_proj1(const float* __restrict__ x,
                                               const float* __restrict__ W1) {
    __shared__ float sx[256 * 25];
    __shared__ float sW[25 * 16];
    int i0 = blockIdx.x * 256;
    int nb = min(256, NN - i0);
    int nf4 = (nb * 25) / 4;
    const float4* xg = (const float4*)(x + (size_t)i0 * 25);
    for (int t = threadIdx.x; t < nf4; t += 256) ((float4*)sx)[t] = __ldcs(xg + t);
    for (int t = threadIdx.x; t < 400; t += 256) sW[t] = W1[t];
    __syncthreads();

    int li = threadIdx.x;
    if (li >= nb) return;
    int i = i0 + li;

    float a[16];
#pragma unroll
    for (int f = 0; f < 16; f++) a[f] = 0.0f;
#pragma unroll
    for (int k = 0; k < 25; k++) {
        float xv = sx[li * 25 + k];
#pragma unroll
        for (int f = 0; f < 16; f++) a[f] = fmaf(xv, sW[k * 16 + f], a[f]);
    }

    float s = rsqrtf(g_deg[i] + 1.0f);
    __half2 hv[8];
#pragma unroll
    for (int q = 0; q < 8; q++)
        hv[q] = __floats2half2_rn(s * a[2*q], s * a[2*q + 1]);

    uint4* hp = (uint4*)(g_hs + (size_t)i * 8);
    uint4* ap = (uint4*)(g_agg + (size_t)i * 8);
    uint4 v0 = *(uint4*)&hv[0];
    uint4 v1 = *(uint4*)&hv[4];
    hp[0] = v0; hp[1] = v1;
    ap[0] = v0; ap[1] = v1;          // self-loop seed (dis*h)
}

__device__ __forceinline__ void red_v4h(__half2* addr, unsigned a, unsigned b,
                                        unsigned c, unsigned d) {
    asm volatile("red.global.add.noftz.v4.f16x2 [%0], {%1,%2,%3,%4};"
                 :: "l"(addr), "r"(a), "r"(b), "r"(c), "r"(d)
                 : "memory");
}

__device__ __forceinline__ void agg1_one(int s, int d, float w) {
    if ((unsigned)s >= NN || (unsigned)d >= NN) return;
    const uint4* hp = (const uint4*)(g_hs + (size_t)s * 8);
    uint4 p0 = __ldg(hp);
    uint4 p1 = __ldg(hp + 1);
    __half2 wh = __float2half2_rn(w);
    __half2* ap = g_agg + (size_t)d * 8;
    unsigned m[8];
    const unsigned* pu = &p0.x;
#pragma unroll
    for (int q = 0; q < 4; q++) {
        __half2 r = __hmul2(wh, *(const __half2*)&pu[q]);
        m[q] = *(unsigned*)&r;
    }
    const unsigned* pv = &p1.x;
#pragma unroll
    for (int q = 0; q < 4; q++) {
        __half2 r = __hmul2(wh, *(const __half2*)&pv[q]);
        m[4 + q] = *(unsigned*)&r;
    }
    red_v4h(ap,     m[0], m[1], m[2], m[3]);
    red_v4h(ap + 4, m[4], m[5], m[6], m[7]);
}

// layer-1 edge scatter: agg[dst] += ew * (dis*h)[src]   (fp16 accumulate)
__global__ void k_agg1(const int4* __restrict__ src4,
                       const int4* __restrict__ dst4,
                       const float4* __restrict__ ew4) {
    int t = blockIdx.x * blockDim.x + threadIdx.x;
    if (t >= NE / 4) return;
    int4 s = __ldcs(src4 + t);
    int4 d = __ldcs(dst4 + t);
    float4 w = __ldcs(ew4 + t);
    agg1_one(s.x, d.x, w.x);
    agg1_one(s.y, d.y, w.y);
    agg1_one(s.z, d.z, w.z);
    agg1_one(s.w, d.w, w.w);
}

// layer1 finish: u = dis[i]*agg + b1 -> ELU -> h2 = u@W2;
// store g_h2s = dis*h2; seed out[i] = g_h2s[i] (pre final dis scale)
__global__ void k_elu_proj2(const float* __restrict__ b1,
                            const float* __restrict__ W2,
                            float* __restrict__ out) {
    __shared__ float sb1[16], sW2[16];
    if (threadIdx.x < 16) { sb1[threadIdx.x] = b1[threadIdx.x]; sW2[threadIdx.x] = W2[threadIdx.x]; }
    __syncthreads();

    int i = blockIdx.x * blockDim.x + threadIdx.x;
    if (i >= NN) return;

    const uint4* ap = (const uint4*)(g_agg + (size_t)i * 8);
    uint4 p0 = ap[0];
    uint4 p1 = ap[1];
    float s = rsqrtf(g_deg[i] + 1.0f);
    float acc = 0.0f;
    const unsigned* pu = &p0.x;
#pragma unroll
    for (int q = 0; q < 4; q++) {
        float2 f = __half22float2(*(const __half2*)&pu[q]);
        float u0 = fmaf(s, f.x, sb1[2*q]);
        float u1 = fmaf(s, f.y, sb1[2*q+1]);
        u0 = (u0 > 0.0f) ? u0 : expm1f(u0);
        u1 = (u1 > 0.0f) ? u1 : expm1f(u1);
        acc = fmaf(u0, sW2[2*q], acc);
        acc = fmaf(u1, sW2[2*q+1], acc);
    }
    const unsigned* pv = &p1.x;
#pragma unroll
    for (int q = 0; q < 4; q++) {
        float2 f = __half22float2(*(const __half2*)&pv[q]);
        float u0 = fmaf(s, f.x, sb1[8+2*q]);
        float u1 = fmaf(s, f.y, sb1[8+2*q+1]);
        u0 = (u0 > 0.0f) ? u0 : expm1f(u0);
        u1 = (u1 > 0.0f) ? u1 : expm1f(u1);
        acc = fmaf(u0, sW2[8+2*q], acc);
        acc = fmaf(u1, sW2[8+2*q+1], acc);
    }
    float hs = s * acc;
    g_h2s[i] = hs;
    out[i] = hs;                                   // self-loop seed
}

__device__ __forceinline__ void red_f32(float* addr, float v) {
    asm volatile("red.global.add.f32 [%0], %1;" :: "l"(addr), "f"(v) : "memory");
}

// layer-2 edge scatter: out[dst] += ew * (dis*h2)[src]   (fp32 accumulate)
__global__ void k_agg2(const int4* __restrict__ src4,
                       const int4* __restrict__ dst4,
                       const float4* __restrict__ ew4,
                       float* __restrict__ out) {
    int t = blockIdx.x * blockDim.x + threadIdx.x;
    if (t >= NE / 4) return;
    int4 s = __ldcs(src4 + t);
    int4 d = __ldcs(dst4 + t);
    float4 w = __ldcs(ew4 + t);
    if ((unsigned)s.x < NN && (unsigned)d.x < NN) red_f32(&out[d.x], w.x * __ldg(&g_h2s[s.x]));
    if ((unsigned)s.y < NN && (unsigned)d.y < NN) red_f32(&out[d.y], w.y * __ldg(&g_h2s[s.y]));
    if ((unsigned)s.z < NN && (unsigned)d.z < NN) red_f32(&out[d.z], w.z * __ldg(&g_h2s[s.z]));
    if ((unsigned)s.w < NN && (unsigned)d.w < NN) red_f32(&out[d.w], w.w * __ldg(&g_h2s[s.w]));
}

// final scale: out = dis*out + b2
__global__ void k_final(float* __restrict__ out, const float* __restrict__ b2) {
    int i = blockIdx.x * blockDim.x + threadIdx.x;
    if (i < NN) out[i] = fmaf(rsqrtf(g_deg[i] + 1.0f), out[i], b2[0]);
}

// ---------------- launch ----------------

extern "C" void kernel_launch(void* const* d_in, const int* in_sizes, int n_in,
                              void* d_out, int out_size) {
    const float* x    = (const float*)d_in[0];
    const int*   eidx = (const int*)d_in[1];      // [2, E] int32
    const float* ew   = (const float*)d_in[2];
    const float* W1   = (const float*)d_in[3];
    const float* b1   = (const float*)d_in[4];
    const float* W2   = (const float*)d_in[5];
    const float* b2   = (const float*)d_in[6];
    float* out = (float*)d_out;

    const int4*   src4 = (const int4*)eidx;
    const int4*   dst4 = (const int4*)(eidx + NE);
    const float4* ew4  = (const float4*)ew;

    const int TB = 256;
    int nb_nodes = (NN + TB - 1) / TB;
    int nb_e4    = (NE / 4 + TB - 1) / TB;

    k_zero<<<nb_nodes, TB>>>();
    k_deg<<<nb_e4, TB>>>(dst4, ew4);
    k_proj1<<<nb_nodes, TB>>>(x, W1);
    k_agg1<<<nb_e4, TB>>>(src4, dst4, ew4);
    k_elu_proj2<<<nb_nodes, TB>>>(b1, W2, out);
    k_agg2<<<nb_e4, TB>>>(src4, dst4, ew4, out);
    k_final<<<nb_nodes, TB>>>(out, b2);
}

// round 6
// speedup vs baseline: 1.7371x; 1.0487x over previous
#include <cuda_runtime.h>
#include <cuda_fp16.h>
#include <math.h>

#define NN 1000000
#define NE 16000000

// ---- scratch (device globals; zero-initialized at load) ----
__device__ float   g_deg[NN];        // re-zeroed by k_final each call
__device__ __half2 g_hs[NN * 8];     // dis[i]*h[i], 16 fp16 features (gather pool, 32MB)
__device__ __half2 g_agg[NN * 8];    // layer-1 accumulation in fp16 (RMW pool, 32MB)
__device__ float   g_h2s[NN];        // dis[i]*h2[i]

// ---------------- kernels ----------------

// per edge: accumulate weighted degree at dst (8 edges/thread)
__global__ void k_deg(const int4* __restrict__ dst4,
                      const float4* __restrict__ ew4) {
    int t = (blockIdx.x * blockDim.x + threadIdx.x) * 2;
    if (t + 1 >= NE / 4 + 1) { /* NE/4 = 4M, even; no tail */ }
#pragma unroll
    for (int j = 0; j < 2; j++) {
        int4 d = __ldcs(dst4 + t + j);
        float4 w = __ldcs(ew4 + t + j);
        if ((unsigned)d.x < NN) atomicAdd(&g_deg[d.x], w.x);
        if ((unsigned)d.y < NN) atomicAdd(&g_deg[d.y], w.y);
        if ((unsigned)d.z < NN) atomicAdd(&g_deg[d.z], w.z);
        if ((unsigned)d.w < NN) atomicAdd(&g_deg[d.w], w.w);
    }
}

// h = x @ W1 (smem-staged x tile); store g_hs = dis*h (fp16), seed g_agg = same (self loop)
__global__ void __launch_bounds__(128) k_proj1(const float* __restrict__ x,
                                               const float* __restrict__ W1) {
    __shared__ float sx[128 * 25];
    __shared__ float sW[25 * 16];
    int i0 = blockIdx.x * 128;
    int nb = min(128, NN - i0);
    int nf4 = (nb * 25) / 4;
    const float4* xg = (const float4*)(x + (size_t)i0 * 25);
    for (int t = threadIdx.x; t < nf4; t += 128) ((float4*)sx)[t] = __ldcs(xg + t);
    for (int t = threadIdx.x; t < 400; t += 128) sW[t] = W1[t];
    __syncthreads();

    int li = threadIdx.x;
    if (li >= nb) return;
    int i = i0 + li;

    float a[16];
#pragma unroll
    for (int f = 0; f < 16; f++) a[f] = 0.0f;
#pragma unroll
    for (int k = 0; k < 25; k++) {
        float xv = sx[li * 25 + k];
#pragma unroll
        for (int f = 0; f < 16; f++) a[f] = fmaf(xv, sW[k * 16 + f], a[f]);
    }

    float s = rsqrtf(g_deg[i] + 1.0f);
    __half2 hv[8];
#pragma unroll
    for (int q = 0; q < 8; q++)
        hv[q] = __floats2half2_rn(s * a[2*q], s * a[2*q + 1]);

    uint4* hp = (uint4*)(g_hs + (size_t)i * 8);
    uint4* ap = (uint4*)(g_agg + (size_t)i * 8);
    uint4 v0 = *(uint4*)&hv[0];
    uint4 v1 = *(uint4*)&hv[4];
    hp[0] = v0; hp[1] = v1;
    ap[0] = v0; ap[1] = v1;          // self-loop seed (dis*h)
}

__device__ __forceinline__ void red_v4h(__half2* addr, unsigned a, unsigned b,
                                        unsigned c, unsigned d) {
    asm volatile("red.global.add.noftz.v4.f16x2 [%0], {%1,%2,%3,%4};"
                 :: "l"(addr), "r"(a), "r"(b), "r"(c), "r"(d)
                 : "memory");
}

// layer-1 edge scatter, paired-lane: 2 lanes per edge, each lane handles 16B
// (consecutive halves of the 32B feature row -> same L2 sector).
__global__ void __launch_bounds__(256) k_agg1(const int* __restrict__ src,
                                              const int* __restrict__ dst,
                                              const float* __restrict__ ew) {
    int half = threadIdx.x & 1;             // which 16B half of the row
    int pair = threadIdx.x >> 1;            // 0..127
    int base = blockIdx.x * 1024;           // 1024 edges per block
#pragma unroll
    for (int j = 0; j < 8; j++) {
        int e = base + j * 128 + pair;
        int s = __ldg(src + e);
        int d = __ldg(dst + e);
        float w = __ldg(ew + e);
        if ((unsigned)s >= NN || (unsigned)d >= NN) continue;
        uint4 p = __ldg((const uint4*)(g_hs + (size_t)s * 8 + half * 4));
        __half2 wh = __float2half2_rn(w);
        const unsigned* pu = &p.x;
        unsigned m[4];
#pragma unroll
        for (int q = 0; q < 4; q++) {
            __half2 r = __hmul2(wh, *(const __half2*)&pu[q]);
            m[q] = *(unsigned*)&r;
        }
        red_v4h(g_agg + (size_t)d * 8 + half * 4, m[0], m[1], m[2], m[3]);
    }
}

// layer1 finish: u = dis[i]*agg + b1 -> ELU -> h2 = u@W2;
// store g_h2s = dis*h2; seed out[i] = g_h2s[i]
__global__ void k_elu_proj2(const float* __restrict__ b1,
                            const float* __restrict__ W2,
                            float* __restrict__ out) {
    __shared__ float sb1[16], sW2[16];
    if (threadIdx.x < 16) { sb1[threadIdx.x] = b1[threadIdx.x]; sW2[threadIdx.x] = W2[threadIdx.x]; }
    __syncthreads();

    int i = blockIdx.x * blockDim.x + threadIdx.x;
    if (i >= NN) return;

    const uint4* ap = (const uint4*)(g_agg + (size_t)i * 8);
    uint4 p0 = ap[0];
    uint4 p1 = ap[1];
    float s = rsqrtf(g_deg[i] + 1.0f);
    float acc = 0.0f;
    const unsigned* pu = &p0.x;
#pragma unroll
    for (int q = 0; q < 4; q++) {
        float2 f = __half22float2(*(const __half2*)&pu[q]);
        float u0 = fmaf(s, f.x, sb1[2*q]);
        float u1 = fmaf(s, f.y, sb1[2*q+1]);
        u0 = (u0 > 0.0f) ? u0 : expm1f(u0);
        u1 = (u1 > 0.0f) ? u1 : expm1f(u1);
        acc = fmaf(u0, sW2[2*q], acc);
        acc = fmaf(u1, sW2[2*q+1], acc);
    }
    const unsigned* pv = &p1.x;
#pragma unroll
    for (int q = 0; q < 4; q++) {
        float2 f = __half22float2(*(const __half2*)&pv[q]);
        float u0 = fmaf(s, f.x, sb1[8+2*q]);
        float u1 = fmaf(s, f.y, sb1[8+2*q+1]);
        u0 = (u0 > 0.0f) ? u0 : expm1f(u0);
        u1 = (u1 > 0.0f) ? u1 : expm1f(u1);
        acc = fmaf(u0, sW2[8+2*q], acc);
        acc = fmaf(u1, sW2[8+2*q+1], acc);
    }
    float hs = s * acc;
    g_h2s[i] = hs;
    out[i] = hs;                                   // self-loop seed
}

__device__ __forceinline__ void red_f32(float* addr, float v) {
    asm volatile("red.global.add.f32 [%0], %1;" :: "l"(addr), "f"(v) : "memory");
}

// layer-2 edge scatter: out[dst] += ew * (dis*h2)[src]   (8 edges/thread)
__global__ void k_agg2(const int4* __restrict__ src4,
                       const int4* __restrict__ dst4,
                       const float4* __restrict__ ew4,
                       float* __restrict__ out) {
    int t = (blockIdx.x * blockDim.x + threadIdx.x) * 2;
#pragma unroll
    for (int j = 0; j < 2; j++) {
        int4 s = __ldcs(src4 + t + j);
        int4 d = __ldcs(dst4 + t + j);
        float4 w = __ldcs(ew4 + t + j);
        if ((unsigned)s.x < NN && (unsigned)d.x < NN) red_f32(&out[d.x], w.x * __ldg(&g_h2s[s.x]));
        if ((unsigned)s.y < NN && (unsigned)d.y < NN) red_f32(&out[d.y], w.y * __ldg(&g_h2s[s.y]));
        if ((unsigned)s.z < NN && (unsigned)d.z < NN) red_f32(&out[d.z], w.z * __ldg(&g_h2s[s.z]));
        if ((unsigned)s.w < NN && (unsigned)d.w < NN) red_f32(&out[d.w], w.w * __ldg(&g_h2s[s.w]));
    }
}

// final scale: out = dis*out + b2; re-zero g_deg for the next call
__global__ void k_final(float* __restrict__ out, const float* __restrict__ b2) {
    int i = blockIdx.x * blockDim.x + threadIdx.x;
    if (i < NN) {
        out[i] = fmaf(rsqrtf(g_deg[i] + 1.0f), out[i], b2[0]);
        g_deg[i] = 0.0f;
    }
}

// ---------------- launch ----------------

extern "C" void kernel_launch(void* const* d_in, const int* in_sizes, int n_in,
                              void* d_out, int out_size) {
    const float* x    = (const float*)d_in[0];
    const int*   eidx = (const int*)d_in[1];      // [2, E] int32
    const float* ew   = (const float*)d_in[2];
    const float* W1   = (const float*)d_in[3];
    const float* b1   = (const float*)d_in[4];
    const float* W2   = (const float*)d_in[5];
    const float* b2   = (const float*)d_in[6];
    float* out = (float*)d_out;

    const int*    src  = eidx;
    const int*    dst  = eidx + NE;
    const int4*   src4 = (const int4*)eidx;
    const int4*   dst4 = (const int4*)(eidx + NE);
    const float4* ew4  = (const float4*)ew;

    const int TB = 256;
    int nb_nodes  = (NN + TB - 1) / TB;
    int nb_e8     = (NE / 8 + TB - 1) / TB;        // 8 edges/thread kernels
    int nb_agg1   = NE / 1024;                     // 1024 edges/block

    k_deg<<<nb_e8, TB>>>(dst4, ew4);
    k_proj1<<<(NN + 127) / 128, 128>>>(x, W1);
    k_agg1<<<nb_agg1, TB>>>(src, dst, ew);
    k_elu_proj2<<<nb_nodes, TB>>>(b1, W2, out);
    k_agg2<<<nb_e8, TB>>>(src4, dst4, ew4, out);
    k_final<<<nb_nodes, TB>>>(out, b2);
}

// round 7
// speedup vs baseline: 1.8044x; 1.0387x over previous
#include <cuda_runtime.h>
#include <cuda_fp16.h>
#include <math.h>

#define NN 1000000
#define NE 16000000

// ---- scratch (device globals; zero-initialized at load) ----
__device__ float   g_deg[NN];        // re-zeroed by k_final each call
__device__ __half2 g_hs[NN * 8];     // h (then dis*h after k_scale), fp16, 32MB
__device__ __half2 g_agg[NN * 8];    // layer-1 accumulation in fp16, 32MB
__device__ float   g_h2s[NN];        // dis[i]*h2[i]

// ---------------- fused: degree atomics (LTS) + x@W1 (DRAM/FMA) ----------------
// blocks with bid%3==0 -> proj (3907), else -> deg (7813). Interleaved so every
// wave mixes both resource profiles.

#define NB_PROJ 3907           // ceil(NN/256)
#define NB_DEG  7813           // ceil((NE/8)/256)
#define NB_FUSED (NB_PROJ + NB_DEG)

__global__ void __launch_bounds__(256) k_fused(const float* __restrict__ x,
                                               const float* __restrict__ W1,
                                               const int4* __restrict__ dst4,
                                               const float4* __restrict__ ew4) {
    int bid = blockIdx.x;
    if (bid % 3 == 0) {
        // ---- projection: h = x @ W1, store UNSCALED fp16 ----
        __shared__ float sx[256 * 25];
        __shared__ float sW[25 * 16];
        int pb = bid / 3;
        int i0 = pb * 256;
        int nb = min(256, NN - i0);
        int nf4 = (nb * 25) / 4;
        const float4* xg = (const float4*)(x + (size_t)i0 * 25);
        for (int t = threadIdx.x; t < nf4; t += 256) ((float4*)sx)[t] = __ldcs(xg + t);
        for (int t = threadIdx.x; t < 400; t += 256) sW[t] = W1[t];
        __syncthreads();

        int li = threadIdx.x;
        if (li >= nb) return;
        int i = i0 + li;

        float a[16];
#pragma unroll
        for (int f = 0; f < 16; f++) a[f] = 0.0f;
#pragma unroll
        for (int k = 0; k < 25; k++) {
            float xv = sx[li * 25 + k];
#pragma unroll
            for (int f = 0; f < 16; f++) a[f] = fmaf(xv, sW[k * 16 + f], a[f]);
        }

        __half2 hv[8];
#pragma unroll
        for (int q = 0; q < 8; q++)
            hv[q] = __floats2half2_rn(a[2*q], a[2*q + 1]);
        uint4* hp = (uint4*)(g_hs + (size_t)i * 8);
        hp[0] = *(uint4*)&hv[0];
        hp[1] = *(uint4*)&hv[4];
    } else {
        // ---- degree accumulation: 8 edges/thread ----
        int db = bid - bid / 3 - 1;
        int t = (db * 256 + threadIdx.x) * 2;
#pragma unroll
        for (int j = 0; j < 2; j++) {
            int tt = t + j;
            if (tt >= NE / 4) break;
            int4 d = __ldcs(dst4 + tt);
            float4 w = __ldcs(ew4 + tt);
            if ((unsigned)d.x < NN) atomicAdd(&g_deg[d.x], w.x);
            if ((unsigned)d.y < NN) atomicAdd(&g_deg[d.y], w.y);
            if ((unsigned)d.z < NN) atomicAdd(&g_deg[d.z], w.z);
            if ((unsigned)d.w < NN) atomicAdd(&g_deg[d.w], w.w);
        }
    }
}

// scale g_hs by dis[i] in place; write agg self-loop seed
__global__ void k_scale() {
    int i = blockIdx.x * blockDim.x + threadIdx.x;
    if (i >= NN) return;
    float s = rsqrtf(g_deg[i] + 1.0f);
    uint4* hp = (uint4*)(g_hs + (size_t)i * 8);
    uint4 p0 = hp[0], p1 = hp[1];
    __half2 hv[8];
    const unsigned* pu = &p0.x;
#pragma unroll
    for (int q = 0; q < 4; q++) {
        float2 f = __half22float2(*(const __half2*)&pu[q]);
        hv[q] = __floats2half2_rn(s * f.x, s * f.y);
    }
    const unsigned* pv = &p1.x;
#pragma unroll
    for (int q = 0; q < 4; q++) {
        float2 f = __half22float2(*(const __half2*)&pv[q]);
        hv[4 + q] = __floats2half2_rn(s * f.x, s * f.y);
    }
    uint4 v0 = *(uint4*)&hv[0];
    uint4 v1 = *(uint4*)&hv[4];
    hp[0] = v0; hp[1] = v1;
    uint4* ap = (uint4*)(g_agg + (size_t)i * 8);
    ap[0] = v0; ap[1] = v1;          // self-loop seed (dis*h)
}

__device__ __forceinline__ void red_v4h(__half2* addr, unsigned a, unsigned b,
                                        unsigned c, unsigned d) {
    asm volatile("red.global.add.noftz.v4.f16x2 [%0], {%1,%2,%3,%4};"
                 :: "l"(addr), "r"(a), "r"(b), "r"(c), "r"(d)
                 : "memory");
}

// layer-1 edge scatter, paired-lane: 2 lanes per edge, each lane handles 16B
__global__ void __launch_bounds__(256) k_agg1(const int* __restrict__ src,
                                              const int* __restrict__ dst,
                                              const float* __restrict__ ew) {
    int half = threadIdx.x & 1;
    int pair = threadIdx.x >> 1;
    int base = blockIdx.x * 1024;
#pragma unroll
    for (int j = 0; j < 8; j++) {
        int e = base + j * 128 + pair;
        int s = __ldg(src + e);
        int d = __ldg(dst + e);
        float w = __ldg(ew + e);
        if ((unsigned)s >= NN || (unsigned)d >= NN) continue;
        uint4 p = __ldg((const uint4*)(g_hs + (size_t)s * 8 + half * 4));
        __half2 wh = __float2half2_rn(w);
        const unsigned* pu = &p.x;
        unsigned m[4];
#pragma unroll
        for (int q = 0; q < 4; q++) {
            __half2 r = __hmul2(wh, *(const __half2*)&pu[q]);
            m[q] = *(unsigned*)&r;
        }
        red_v4h(g_agg + (size_t)d * 8 + half * 4, m[0], m[1], m[2], m[3]);
    }
}

// layer1 finish: u = dis[i]*agg + b1 -> ELU -> h2 = u@W2
__global__ void k_elu_proj2(const float* __restrict__ b1,
                            const float* __restrict__ W2,
                            float* __restrict__ out) {
    __shared__ float sb1[16], sW2[16];
    if (threadIdx.x < 16) { sb1[threadIdx.x] = b1[threadIdx.x]; sW2[threadIdx.x] = W2[threadIdx.x]; }
    __syncthreads();

    int i = blockIdx.x * blockDim.x + threadIdx.x;
    if (i >= NN) return;

    const uint4* ap = (const uint4*)(g_agg + (size_t)i * 8);
    uint4 p0 = ap[0];
    uint4 p1 = ap[1];
    float s = rsqrtf(g_deg[i] + 1.0f);
    float acc = 0.0f;
    const unsigned* pu = &p0.x;
#pragma unroll
    for (int q = 0; q < 4; q++) {
        float2 f = __half22float2(*(const __half2*)&pu[q]);
        float u0 = fmaf(s, f.x, sb1[2*q]);
        float u1 = fmaf(s, f.y, sb1[2*q+1]);
        u0 = (u0 > 0.0f) ? u0 : (__expf(u0) - 1.0f);
        u1 = (u1 > 0.0f) ? u1 : (__expf(u1) - 1.0f);
        acc = fmaf(u0, sW2[2*q], acc);
        acc = fmaf(u1, sW2[2*q+1], acc);
    }
    const unsigned* pv = &p1.x;
#pragma unroll
    for (int q = 0; q < 4; q++) {
        float2 f = __half22float2(*(const __half2*)&pv[q]);
        float u0 = fmaf(s, f.x, sb1[8+2*q]);
        float u1 = fmaf(s, f.y, sb1[8+2*q+1]);
        u0 = (u0 > 0.0f) ? u0 : (__expf(u0) - 1.0f);
        u1 = (u1 > 0.0f) ? u1 : (__expf(u1) - 1.0f);
        acc = fmaf(u0, sW2[8+2*q], acc);
        acc = fmaf(u1, sW2[8+2*q+1], acc);
    }
    float hs = s * acc;
    g_h2s[i] = hs;
    out[i] = hs;                                   // self-loop seed
}

__device__ __forceinline__ void red_f32(float* addr, float v) {
    asm volatile("red.global.add.f32 [%0], %1;" :: "l"(addr), "f"(v) : "memory");
}

// layer-2 edge scatter: out[dst] += ew * (dis*h2)[src]   (8 edges/thread)
__global__ void k_agg2(const int4* __restrict__ src4,
                       const int4* __restrict__ dst4,
                       const float4* __restrict__ ew4,
                       float* __restrict__ out) {
    int t = (blockIdx.x * blockDim.x + threadIdx.x) * 2;
#pragma unroll
    for (int j = 0; j < 2; j++) {
        int tt = t + j;
        if (tt >= NE / 4) break;
        int4 s = __ldcs(src4 + tt);
        int4 d = __ldcs(dst4 + tt);
        float4 w = __ldcs(ew4 + tt);
        if ((unsigned)s.x < NN && (unsigned)d.x < NN) red_f32(&out[d.x], w.x * __ldg(&g_h2s[s.x]));
        if ((unsigned)s.y < NN && (unsigned)d.y < NN) red_f32(&out[d.y], w.y * __ldg(&g_h2s[s.y]));
        if ((unsigned)s.z < NN && (unsigned)d.z < NN) red_f32(&out[d.z], w.z * __ldg(&g_h2s[s.z]));
        if ((unsigned)s.w < NN && (unsigned)d.w < NN) red_f32(&out[d.w], w.w * __ldg(&g_h2s[s.w]));
    }
}

// final scale: out = dis*out + b2; re-zero g_deg for the next call
__global__ void k_final(float* __restrict__ out, const float* __restrict__ b2) {
    int i = blockIdx.x * blockDim.x + threadIdx.x;
    if (i < NN) {
        out[i] = fmaf(rsqrtf(g_deg[i] + 1.0f), out[i], b2[0]);
        g_deg[i] = 0.0f;
    }
}

// ---------------- launch ----------------

extern "C" void kernel_launch(void* const* d_in, const int* in_sizes, int n_in,
                              void* d_out, int out_size) {
    const float* x    = (const float*)d_in[0];
    const int*   eidx = (const int*)d_in[1];      // [2, E] int32
    const float* ew   = (const float*)d_in[2];
    const float* W1   = (const float*)d_in[3];
    const float* b1   = (const float*)d_in[4];
    const float* W2   = (const float*)d_in[5];
    const float* b2   = (const float*)d_in[6];
    float* out = (float*)d_out;

    const int*    src  = eidx;
    const int*    dst  = eidx + NE;
    const int4*   src4 = (const int4*)eidx;
    const int4*   dst4 = (const int4*)(eidx + NE);
    const float4* ew4  = (const float4*)ew;

    const int TB = 256;
    int nb_nodes = (NN + TB - 1) / TB;
    int nb_e8    = (NE / 8 + TB - 1) / TB;
    int nb_agg1  = NE / 1024;

    k_fused<<<NB_FUSED, TB>>>(x, W1, dst4, ew4);
    k_scale<<<nb_nodes, TB>>>();
    k_agg1<<<nb_agg1, TB>>>(src, dst, ew);
    k_elu_proj2<<<nb_nodes, TB>>>(b1, W2, out);
    k_agg2<<<nb_e8, TB>>>(src4, dst4, ew4, out);
    k_final<<<nb_nodes, TB>>>(out, b2);
}